// round 2
// baseline (speedup 1.0000x reference)
#include <cuda_runtime.h>
#include <math.h>

#define LSEQ    4096
#define DMODEL  512
#define NHEADS  8
#define BATCH   2
#define BHN     16          // BATCH*NHEADS
#define DH      64
#define NTOPMAX 48
#define SPLITS  16
#define CHUNK   256         // LSEQ / SPLITS
#define TILE    32
#define SCALE   0.125f      // 1/sqrt(64)

// ---------------- scratch (static device globals; no allocations) ----------
__device__ float g_q[BHN * LSEQ * DH];
__device__ float g_k[BHN * LSEQ * DH];
__device__ float g_v[BHN * LSEQ * DH];
__device__ float g_m[BHN * LSEQ];
__device__ int   g_top[BHN * NTOPMAX];
__device__ float g_pm[BHN * SPLITS * NTOPMAX];
__device__ float g_pl[BHN * SPLITS * NTOPMAX];
__device__ float g_pacc[BHN * SPLITS * NTOPMAX * DH];
__device__ float g_upd[BHN * NTOPMAX * DH];
__device__ float g_csum[BHN * 64 * DH];

// ---------------- Phase A: fused Q/K/V projection GEMMs (fp32 tiled) -------
// out[m,n] = sum_k A[m,k] * W[k,n] + bias[n], stored to head layout
// g_X[(b*8+h)*LSEQ*64 + l*64 + d] where m=b*4096+l, n=h*64+d.
__global__ __launch_bounds__(256) void proj_gemm(
    const float* __restrict__ in_q, const float* __restrict__ in_k,
    const float* __restrict__ in_v,
    const float* __restrict__ Wq, const float* __restrict__ bq,
    const float* __restrict__ Wk, const float* __restrict__ bk,
    const float* __restrict__ Wv, const float* __restrict__ bv)
{
    const float *A, *W, *bias;
    float *O;
    if (blockIdx.z == 0)      { A = in_q; W = Wq; bias = bq; O = g_q; }
    else if (blockIdx.z == 1) { A = in_k; W = Wk; bias = bk; O = g_k; }
    else                      { A = in_v; W = Wv; bias = bv; O = g_v; }

    __shared__ float As[8][128];   // As[k][m]
    __shared__ float Bs[8][128];   // Bs[k][n]

    const int tid  = threadIdx.x;
    const int m0   = blockIdx.y * 128;
    const int n0   = blockIdx.x * 128;
    const int tx   = tid & 15;
    const int ty   = tid >> 4;
    const int arow = tid >> 1;
    const int ac4  = (tid & 1) * 4;
    const int brow = tid >> 5;
    const int bc4  = (tid & 31) * 4;

    float acc[8][8];
#pragma unroll
    for (int i = 0; i < 8; i++)
#pragma unroll
        for (int j = 0; j < 8; j++) acc[i][j] = 0.f;

    for (int k0 = 0; k0 < DMODEL; k0 += 8) {
        float4 a4 = *(const float4*)(A + (size_t)(m0 + arow) * DMODEL + k0 + ac4);
        As[ac4 + 0][arow] = a4.x;
        As[ac4 + 1][arow] = a4.y;
        As[ac4 + 2][arow] = a4.z;
        As[ac4 + 3][arow] = a4.w;
        float4 b4 = *(const float4*)(W + (size_t)(k0 + brow) * DMODEL + n0 + bc4);
        *(float4*)&Bs[brow][bc4] = b4;
        __syncthreads();
#pragma unroll
        for (int kk = 0; kk < 8; kk++) {
            float am[8], bn[8];
#pragma unroll
            for (int i = 0; i < 8; i++) am[i] = As[kk][ty * 8 + i];
#pragma unroll
            for (int j = 0; j < 8; j++) bn[j] = Bs[kk][tx * 8 + j];
#pragma unroll
            for (int i = 0; i < 8; i++)
#pragma unroll
                for (int j = 0; j < 8; j++) acc[i][j] += am[i] * bn[j];
        }
        __syncthreads();
    }

#pragma unroll
    for (int i = 0; i < 8; i++) {
        int m = m0 + ty * 8 + i;
        int b = m >> 12;
        int l = m & (LSEQ - 1);
#pragma unroll
        for (int j = 0; j < 8; j++) {
            int n  = n0 + tx * 8 + j;
            int hh = n >> 6;
            int dd = n & 63;
            O[((size_t)(b * NHEADS + hh) * LSEQ + l) * DH + dd] = acc[i][j] + bias[n];
        }
    }
}

// ---------------- Phase B: sampled sparsity measure m ----------------------
// one warp per (bh, l): m[l] = max_s(q_l . k_idx[s]) - sum_s(...)/LSEQ
__global__ __launch_bounds__(128) void sample_m(const int* __restrict__ idxs, int S)
{
    int bh   = blockIdx.y;
    int l    = blockIdx.x * 4 + (threadIdx.x >> 5);
    int lane = threadIdx.x & 31;

    const float* qrow = g_q + ((size_t)bh * LSEQ + l) * DH;
    float q0 = qrow[lane * 2], q1 = qrow[lane * 2 + 1];

    float mx = -INFINITY, sm = 0.f;
    const int* ip = idxs + (size_t)l * S;
    for (int s = 0; s < S; s++) {
        int j = ip[s];
        const float* krow = g_k + ((size_t)bh * LSEQ + j) * DH;
        float p = q0 * krow[lane * 2] + q1 * krow[lane * 2 + 1];
#pragma unroll
        for (int off = 16; off; off >>= 1) p += __shfl_xor_sync(0xffffffffu, p, off);
        mx = fmaxf(mx, p);
        sm += p;
    }
    if (lane == 0) g_m[(size_t)bh * LSEQ + l] = mx - sm * (1.0f / LSEQ);
}

// ---------------- Phase C: top-ntop selection per (b,h) --------------------
__global__ __launch_bounds__(256) void topk_sel(int ntop)
{
    int bh  = blockIdx.x;
    int tid = threadIdx.x;
    __shared__ float sv[LSEQ];
    __shared__ float wv[8];
    __shared__ int   wi[8];

    for (int i = tid; i < LSEQ; i += 256) sv[i] = g_m[(size_t)bh * LSEQ + i];
    __syncthreads();

    for (int t = 0; t < ntop; t++) {
        float best = -3.4e38f;
        int   bi   = 0;
        for (int i = tid; i < LSEQ; i += 256)
            if (sv[i] > best) { best = sv[i]; bi = i; }
#pragma unroll
        for (int off = 16; off; off >>= 1) {
            float ov = __shfl_xor_sync(0xffffffffu, best, off);
            int   oi = __shfl_xor_sync(0xffffffffu, bi, off);
            if (ov > best) { best = ov; bi = oi; }
        }
        if ((tid & 31) == 0) { wv[tid >> 5] = best; wi[tid >> 5] = bi; }
        __syncthreads();
        if (tid == 0) {
            float bb = wv[0]; int bj = wi[0];
            for (int w = 1; w < 8; w++)
                if (wv[w] > bb) { bb = wv[w]; bj = wi[w]; }
            g_top[bh * NTOPMAX + t] = bj;
            sv[bj] = -3.4e38f;
        }
        __syncthreads();
    }
}

// ---------------- Phase D1: split-K flash attention for top queries --------
__global__ __launch_bounds__(256) void flash_part(int ntop)
{
    int bh  = blockIdx.y;
    int c   = blockIdx.x;          // key split
    int tid = threadIdx.x;

    __shared__ float qs[NTOPMAX * 65];
    __shared__ float Ks[TILE * 65];
    __shared__ float Vs[TILE * 65];
    __shared__ float sc[NTOPMAX * TILE];
    __shared__ int   pos[NTOPMAX];
    __shared__ int   smaxpos;

    if (tid < ntop) pos[tid] = g_top[bh * NTOPMAX + tid];
    __syncthreads();
    if (tid == 0) {
        int mp = 0;
        for (int u2 = 0; u2 < ntop; u2++) mp = max(mp, pos[u2]);
        smaxpos = mp;
    }
    for (int i = tid; i < ntop * DH; i += 256) {
        int u2 = i >> 6, d = i & 63;
        qs[u2 * 65 + d] = g_q[((size_t)bh * LSEQ + pos[u2]) * DH + d];
    }
    __syncthreads();
    const int maxpos = smaxpos;

    const int u      = tid >> 2;     // query row this thread's team owns
    const int qt     = tid & 3;      // quarter of the 64 output channels
    const bool active = (u < ntop);
    const int mypos  = active ? pos[u] : -1;

    float accv[16];
#pragma unroll
    for (int i = 0; i < 16; i++) accv[i] = 0.f;
    float rm = -INFINITY, rl = 0.f;

    for (int t = 0; t < CHUNK / TILE; t++) {
        int j0 = c * CHUNK + t * TILE;
        if (j0 > maxpos) break;

        for (int i = tid; i < TILE * DH; i += 256) {
            int r = i >> 6, d = i & 63;
            Ks[r * 65 + d] = g_k[((size_t)bh * LSEQ + j0 + r) * DH + d];
            Vs[r * 65 + d] = g_v[((size_t)bh * LSEQ + j0 + r) * DH + d];
        }
        __syncthreads();

        // scores: each thread computes 4 keys for one query
        for (int p = tid; p < ntop * (TILE / 4); p += 256) {
            int uu = p >> 3;
            int jq = (p & 7) * 4;
            const float* qrow = qs + uu * 65;
            float s0 = 0, s1 = 0, s2 = 0, s3 = 0;
#pragma unroll
            for (int d = 0; d < DH; d++) {
                float qv = qrow[d];
                s0 += qv * Ks[(jq + 0) * 65 + d];
                s1 += qv * Ks[(jq + 1) * 65 + d];
                s2 += qv * Ks[(jq + 2) * 65 + d];
                s3 += qv * Ks[(jq + 3) * 65 + d];
            }
            int pu = pos[uu];
            sc[uu * TILE + jq + 0] = (j0 + jq + 0 <= pu) ? s0 * SCALE : -INFINITY;
            sc[uu * TILE + jq + 1] = (j0 + jq + 1 <= pu) ? s1 * SCALE : -INFINITY;
            sc[uu * TILE + jq + 2] = (j0 + jq + 2 <= pu) ? s2 * SCALE : -INFINITY;
            sc[uu * TILE + jq + 3] = (j0 + jq + 3 <= pu) ? s3 * SCALE : -INFINITY;
        }
        __syncthreads();

        if (active && j0 <= mypos) {
            const float* srow = sc + u * TILE;
            float tm = -INFINITY;
#pragma unroll
            for (int j = 0; j < TILE; j++) tm = fmaxf(tm, srow[j]);
            if (tm != -INFINITY) {
                float nm    = fmaxf(rm, tm);
                float alpha = __expf(rm - nm);   // rm=-inf -> 0
                rl *= alpha;
#pragma unroll
                for (int i = 0; i < 16; i++) accv[i] *= alpha;
                float psum = 0.f;
                for (int j = 0; j < TILE; j++) {
                    float pj = __expf(srow[j] - nm);   // -inf -> 0
                    psum += pj;
                    const float* vrow = Vs + j * 65 + qt * 16;
#pragma unroll
                    for (int i = 0; i < 16; i++) accv[i] += pj * vrow[i];
                }
                rl += psum;
                rm = nm;
            }
        }
        __syncthreads();
    }

    if (active) {
        int base = (bh * SPLITS + c) * NTOPMAX + u;
        if (qt == 0) { g_pm[base] = rm; g_pl[base] = rl; }
        float* pa = g_pacc + (size_t)base * DH + qt * 16;
#pragma unroll
        for (int i = 0; i < 16; i++) pa[i] = accv[i];
    }
}

// ---------------- Phase D2: combine split-K partials -----------------------
__global__ __launch_bounds__(64) void flash_reduce(int ntop)
{
    int u = blockIdx.x, bh = blockIdx.y, d = threadIdx.x;
    float M = -INFINITY;
    for (int cc = 0; cc < SPLITS; cc++)
        M = fmaxf(M, g_pm[(bh * SPLITS + cc) * NTOPMAX + u]);
    float Ls = 0.f, od = 0.f;
    for (int cc = 0; cc < SPLITS; cc++) {
        int base  = (bh * SPLITS + cc) * NTOPMAX + u;
        float pmv = g_pm[base];
        if (pmv == -INFINITY) continue;
        float w = __expf(pmv - M);
        Ls += g_pl[base] * w;
        od += g_pacc[(size_t)base * DH + d] * w;
    }
    g_upd[(bh * NTOPMAX + u) * DH + d] = od / Ls;
}

// ---------------- Phase E: cumsum(v) over L, two-pass scan -----------------
__global__ __launch_bounds__(64) void chunk_sums()
{
    int bh = blockIdx.y, c = blockIdx.x, d = threadIdx.x;
    const float* vp = g_v + ((size_t)bh * LSEQ + c * 64) * DH + d;
    float s = 0.f;
#pragma unroll 8
    for (int r = 0; r < 64; r++) s += vp[(size_t)r * DH];
    g_csum[(bh * 64 + c) * DH + d] = s;
}

__global__ __launch_bounds__(64) void cumsum_out(float* __restrict__ out)
{
    int bh = blockIdx.y, c = blockIdx.x, d = threadIdx.x;
    float off = 0.f;
    for (int cc = 0; cc < c; cc++) off += g_csum[(bh * 64 + cc) * DH + d];
    const float* vp = g_v + ((size_t)bh * LSEQ + c * 64) * DH + d;
    int b = bh >> 3, h = bh & 7;
    float* op = out + ((size_t)b * LSEQ + c * 64) * DMODEL + h * DH + d;
    float acc = off;
    for (int r = 0; r < 64; r++) {
        acc += vp[(size_t)r * DH];
        op[(size_t)r * DMODEL] = acc;
    }
}

// ---------------- Phase F: scatter attention rows over cumsum --------------
__global__ __launch_bounds__(64) void scatter_upd(float* __restrict__ out, int ntop)
{
    int u = blockIdx.x, bh = blockIdx.y, d = threadIdx.x;
    int b = bh >> 3, h = bh & 7;
    int p = g_top[bh * NTOPMAX + u];
    out[((size_t)b * LSEQ + p) * DMODEL + h * DH + d] =
        g_upd[(bh * NTOPMAX + u) * DH + d];
}

// ---------------- launch ---------------------------------------------------
extern "C" void kernel_launch(void* const* d_in, const int* in_sizes, int n_in,
                              void* d_out, int out_size)
{
    const float* q_in = (const float*)d_in[0];
    const float* k_in = (const float*)d_in[1];
    const float* v_in = (const float*)d_in[2];
    const float* Wq   = (const float*)d_in[3];
    const float* bq   = (const float*)d_in[4];
    const float* Wk   = (const float*)d_in[5];
    const float* bk   = (const float*)d_in[6];
    const float* Wv   = (const float*)d_in[7];
    const float* bv   = (const float*)d_in[8];
    const int*   idxs = (const int*)d_in[9];
    float*       out  = (float*)d_out;

    int S    = in_sizes[9] / LSEQ;   // 45
    int ntop = S < NTOPMAX ? S : NTOPMAX;

    proj_gemm<<<dim3(DMODEL / 128, (BATCH * LSEQ) / 128, 3), 256>>>(
        q_in, k_in, v_in, Wq, bq, Wk, bk, Wv, bv);
    sample_m<<<dim3(LSEQ / 4, BHN), 128>>>(idxs, S);
    topk_sel<<<BHN, 256>>>(ntop);
    flash_part<<<dim3(SPLITS, BHN), 256>>>(ntop);
    flash_reduce<<<dim3(ntop, BHN), 64>>>(ntop);
    chunk_sums<<<dim3(64, BHN), 64>>>();
    cumsum_out<<<dim3(64, BHN), 64>>>(out);
    scatter_upd<<<dim3(ntop, BHN), 64>>>(out, ntop);
}

// round 6
// speedup vs baseline: 1.3864x; 1.3864x over previous
#include <cuda_runtime.h>
#include <cuda_bf16.h>
#include <math.h>
#include <stdint.h>

#define LSEQ    4096
#define DMODEL  512
#define NHEADS  8
#define BATCH   2
#define BHN     16          // BATCH*NHEADS
#define DH      64
#define NTOPMAX 48
#define SPLITS  16
#define CHUNK   256         // LSEQ / SPLITS
#define TILE    32
#define SCALE   0.125f      // 1/sqrt(64)

#define MTOT    (BATCH * LSEQ)      // 8192

// ---------------- scratch (static device globals; no allocations) ----------
__device__ float g_q[BHN * LSEQ * DH];
__device__ float g_k[BHN * LSEQ * DH];
__device__ float g_v[BHN * LSEQ * DH];
__device__ float g_m[BHN * LSEQ];
__device__ int   g_top[BHN * NTOPMAX];
__device__ float g_pm[BHN * SPLITS * NTOPMAX];
__device__ float g_pl[BHN * SPLITS * NTOPMAX];
__device__ float g_pacc[BHN * SPLITS * NTOPMAX * DH];
__device__ float g_upd[BHN * NTOPMAX * DH];
__device__ float g_csum[BHN * 64 * DH];

// bf16 split operands for tensor-core projections
__device__ __nv_bfloat16 g_ah[3ull * MTOT * DMODEL];    // A hi  [m][k]
__device__ __nv_bfloat16 g_al[3ull * MTOT * DMODEL];    // A lo  [m][k]
__device__ __nv_bfloat16 g_bh[3ull * DMODEL * DMODEL];  // W^T hi [n][k]
__device__ __nv_bfloat16 g_bl[3ull * DMODEL * DMODEL];  // W^T lo [n][k]

// ---------------- small PTX helpers (sm_103 baseline, no 'a' features) -----
__device__ __forceinline__ uint32_t smem_u32(const void* p) {
    uint32_t a;
    asm("{ .reg .u64 t; cvta.to.shared.u64 t, %1; cvt.u32.u64 %0, t; }"
        : "=r"(a) : "l"(p));
    return a;
}
__device__ __forceinline__ void cp16(uint32_t dst, const void* src) {
    asm volatile("cp.async.cg.shared.global [%0], [%1], 16;"
                 :: "r"(dst), "l"(src));
}
__device__ __forceinline__ void cp_commit() {
    asm volatile("cp.async.commit_group;" ::: "memory");
}
template <int N>
__device__ __forceinline__ void cp_wait() {
    asm volatile("cp.async.wait_group %0;" :: "n"(N) : "memory");
}
__device__ __forceinline__ void ldsm4(uint32_t* r, uint32_t addr) {
    asm volatile("ldmatrix.sync.aligned.m8n8.x4.shared.b16 {%0,%1,%2,%3}, [%4];"
                 : "=r"(r[0]), "=r"(r[1]), "=r"(r[2]), "=r"(r[3]) : "r"(addr));
}
__device__ __forceinline__ void mma16816(float* c, const uint32_t* a,
                                         const uint32_t* b) {
    asm volatile(
        "mma.sync.aligned.m16n8k16.row.col.f32.bf16.bf16.f32 "
        "{%0,%1,%2,%3}, {%4,%5,%6,%7}, {%8,%9}, {%0,%1,%2,%3};"
        : "+f"(c[0]), "+f"(c[1]), "+f"(c[2]), "+f"(c[3])
        : "r"(a[0]), "r"(a[1]), "r"(a[2]), "r"(a[3]), "r"(b[0]), "r"(b[1]));
}

// ---------------- Phase A0: convert inputs to bf16 split -------------------
__global__ __launch_bounds__(256) void convert_A(
    const float* __restrict__ q, const float* __restrict__ k,
    const float* __restrict__ v)
{
    int z = blockIdx.z;
    const float* src = (z == 0) ? q : (z == 1) ? k : v;
    __nv_bfloat16* oh = g_ah + (size_t)z * MTOT * DMODEL;
    __nv_bfloat16* ol = g_al + (size_t)z * MTOT * DMODEL;
    size_t idx = ((size_t)blockIdx.x * 256 + threadIdx.x) * 4;
    float4 x = *(const float4*)(src + idx);
    float xs[4] = {x.x, x.y, x.z, x.w};
#pragma unroll
    for (int i = 0; i < 4; i++) {
        __nv_bfloat16 h = __float2bfloat16(xs[i]);
        __nv_bfloat16 l = __float2bfloat16(xs[i] - __bfloat162float(h));
        oh[idx + i] = h;
        ol[idx + i] = l;
    }
}

__global__ __launch_bounds__(256) void convert_W(
    const float* __restrict__ Wq, const float* __restrict__ Wk,
    const float* __restrict__ Wv)
{
    int z = blockIdx.z;
    const float* W = (z == 0) ? Wq : (z == 1) ? Wk : Wv;
    size_t idx = (size_t)blockIdx.x * 256 + threadIdx.x;   // over 512*512
    int kk = (int)(idx >> 9);
    int n  = (int)(idx & 511);
    float x = W[idx];                                      // W[k][n]
    __nv_bfloat16 h = __float2bfloat16(x);
    __nv_bfloat16 l = __float2bfloat16(x - __bfloat162float(h));
    size_t o = (size_t)z * DMODEL * DMODEL + (size_t)n * DMODEL + kk;
    g_bh[o] = h;
    g_bl[o] = l;
}

// ---------------- Phase A: mma.sync bf16-split projection GEMM -------------
// 128x128 CTA tile, BK=32, 8 warps (4x2), warp tile 32x64.
// out = A @ W + bias; error term lo*lo dropped (≈2^-16 relative).
#define BK          32
#define ROWB        80                    // padded smem row bytes (32 bf16 + 16B)
#define MAT_BYTES   (128 * ROWB)          // 10240
#define STAGE_BYTES (4 * MAT_BYTES)       // Ah, Al, Bh, Bl
#define PROJ_SMEM   (2 * STAGE_BYTES)     // 81920

__global__ __launch_bounds__(256, 1)
void proj_tc(const float* __restrict__ bq, const float* __restrict__ bk,
             const float* __restrict__ bv)
{
    extern __shared__ char sm[];
    const int tid    = threadIdx.x;
    const int lane   = tid & 31;
    const int wid    = tid >> 5;
    const int warp_m = wid >> 1;          // 0..3
    const int warp_n = wid & 1;           // 0..1
    const int z      = blockIdx.z;
    const int m0     = blockIdx.y * 128;
    const int n0     = blockIdx.x * 128;

    const __nv_bfloat16* gsrc[4];
    gsrc[0] = g_ah + (size_t)z * MTOT * DMODEL + (size_t)m0 * DMODEL;
    gsrc[1] = g_al + (size_t)z * MTOT * DMODEL + (size_t)m0 * DMODEL;
    gsrc[2] = g_bh + (size_t)z * DMODEL * DMODEL + (size_t)n0 * DMODEL;
    gsrc[3] = g_bl + (size_t)z * DMODEL * DMODEL + (size_t)n0 * DMODEL;
    const float* bias = (z == 0) ? bq : (z == 1) ? bk : bv;
    float* O          = (z == 0) ? g_q : (z == 1) ? g_k : g_v;

    const uint32_t sbase = smem_u32(sm);

    // per-thread cp.async assignment: 2048 16B copies / 256 threads = 8
    const int ld_mat = tid >> 6;            // reuse pattern below instead
    (void)ld_mat;

    float acc[2][8][4];
#pragma unroll
    for (int mi = 0; mi < 2; mi++)
#pragma unroll
        for (int j = 0; j < 8; j++)
#pragma unroll
            for (int r = 0; r < 4; r++) acc[mi][j][r] = 0.f;

    // ldmatrix per-lane address components
    const uint32_t aRow  = lane & 15;
    const uint32_t aHalf = (lane >> 4) * 16;
    const uint32_t bRow  = (lane & 7) + ((lane >> 4) << 3);
    const uint32_t bHalf = ((lane >> 3) & 1) * 16;

    const uint32_t aBase = sbase + 0 * MAT_BYTES;  // Ah (Al = +MAT_BYTES)
    const uint32_t bBase = sbase + 2 * MAT_BYTES;  // Bh (Bl = +MAT_BYTES)

    // ---- stage loader ----
    auto load_stage = [&](int stage, int k0) {
#pragma unroll
        for (int t = 0; t < 8; t++) {
            int linear = tid + t * 256;          // 0..2047
            int mat    = linear >> 9;            // 0..3
            int rem    = linear & 511;
            int row    = rem >> 2;               // 0..127
            int q4     = rem & 3;                // 16B quarter
            uint32_t dst = sbase + stage * STAGE_BYTES + mat * MAT_BYTES
                         + row * ROWB + q4 * 16;
            cp16(dst, gsrc[mat] + (size_t)row * DMODEL + k0 + q4 * 8);
        }
        cp_commit();
    };

    load_stage(0, 0);

    for (int c = 0; c < DMODEL / BK; c++) {     // 16 chunks of 32
        if (c + 1 < DMODEL / BK) {
            load_stage((c + 1) & 1, (c + 1) * BK);
            cp_wait<1>();
        } else {
            cp_wait<0>();
        }
        __syncthreads();

        const uint32_t st = ((uint32_t)(c & 1)) * STAGE_BYTES;

#pragma unroll
        for (int ks = 0; ks < 2; ks++) {        // two k16 steps
            uint32_t ah[2][4], al[2][4];
#pragma unroll
            for (int mi = 0; mi < 2; mi++) {
                uint32_t ra = st + (warp_m * 32 + mi * 16 + aRow) * ROWB
                            + aHalf + ks * 32;
                ldsm4(ah[mi], aBase + ra);
                ldsm4(al[mi], aBase + MAT_BYTES + ra);
            }
            uint32_t bh[4][4], bl[4][4];
#pragma unroll
            for (int j2 = 0; j2 < 4; j2++) {
                uint32_t rb = st + (warp_n * 64 + j2 * 16 + bRow) * ROWB
                            + bHalf + ks * 32;
                ldsm4(bh[j2], bBase + rb);
                ldsm4(bl[j2], bBase + MAT_BYTES + rb);
            }
#pragma unroll
            for (int mi = 0; mi < 2; mi++)
#pragma unroll
                for (int j = 0; j < 8; j++) {
                    const uint32_t* ph = &bh[j >> 1][(j & 1) * 2];
                    const uint32_t* pl = &bl[j >> 1][(j & 1) * 2];
                    mma16816(acc[mi][j], ah[mi], ph);   // hi*hi
                    mma16816(acc[mi][j], ah[mi], pl);   // hi*lo
                    mma16816(acc[mi][j], al[mi], ph);   // lo*hi
                }
        }
        __syncthreads();
    }

    // ---- epilogue: fragments -> head-layout global, + bias ----
#pragma unroll
    for (int mi = 0; mi < 2; mi++) {
        int row0 = m0 + warp_m * 32 + mi * 16 + (lane >> 2);
#pragma unroll
        for (int j = 0; j < 8; j++) {
            int n  = n0 + warp_n * 64 + j * 8 + (lane & 3) * 2;
            int hh = n >> 6;
            int dd = n & 63;
            float b0 = bias[n], b1 = bias[n + 1];
#pragma unroll
            for (int half = 0; half < 2; half++) {
                int m = row0 + half * 8;
                int bb = m >> 12;
                int l  = m & (LSEQ - 1);
                float2 val;
                val.x = acc[mi][j][half * 2 + 0] + b0;
                val.y = acc[mi][j][half * 2 + 1] + b1;
                *(float2*)(O + ((size_t)(bb * NHEADS + hh) * LSEQ + l) * DH + dd)
                    = val;
            }
        }
    }
}

// ---------------- Phase B: sampled sparsity measure m ----------------------
__global__ __launch_bounds__(128) void sample_m(const int* __restrict__ idxs, int S)
{
    int bh   = blockIdx.y;
    int l    = blockIdx.x * 4 + (threadIdx.x >> 5);
    int lane = threadIdx.x & 31;

    const float* qrow = g_q + ((size_t)bh * LSEQ + l) * DH;
    float q0 = qrow[lane * 2], q1 = qrow[lane * 2 + 1];

    float mx = -INFINITY, sm = 0.f;
    const int* ip = idxs + (size_t)l * S;
    for (int s = 0; s < S; s++) {
        int j = ip[s];
        const float* krow = g_k + ((size_t)bh * LSEQ + j) * DH;
        float p = q0 * krow[lane * 2] + q1 * krow[lane * 2 + 1];
#pragma unroll
        for (int off = 16; off; off >>= 1) p += __shfl_xor_sync(0xffffffffu, p, off);
        mx = fmaxf(mx, p);
        sm += p;
    }
    if (lane == 0) g_m[(size_t)bh * LSEQ + l] = mx - sm * (1.0f / LSEQ);
}

// ---------------- Phase C: top-ntop selection per (b,h) --------------------
__global__ __launch_bounds__(256) void topk_sel(int ntop)
{
    int bh  = blockIdx.x;
    int tid = threadIdx.x;
    __shared__ float sv[LSEQ];
    __shared__ float wv[8];
    __shared__ int   wi[8];

    for (int i = tid; i < LSEQ; i += 256) sv[i] = g_m[(size_t)bh * LSEQ + i];
    __syncthreads();

    for (int t = 0; t < ntop; t++) {
        float best = -3.4e38f;
        int   bi   = 0;
        for (int i = tid; i < LSEQ; i += 256)
            if (sv[i] > best) { best = sv[i]; bi = i; }
#pragma unroll
        for (int off = 16; off; off >>= 1) {
            float ov = __shfl_xor_sync(0xffffffffu, best, off);
            int   oi = __shfl_xor_sync(0xffffffffu, bi, off);
            if (ov > best) { best = ov; bi = oi; }
        }
        if ((tid & 31) == 0) { wv[tid >> 5] = best; wi[tid >> 5] = bi; }
        __syncthreads();
        if (tid == 0) {
            float bb = wv[0]; int bj = wi[0];
            for (int w = 1; w < 8; w++)
                if (wv[w] > bb) { bb = wv[w]; bj = wi[w]; }
            g_top[bh * NTOPMAX + t] = bj;
            sv[bj] = -3.4e38f;
        }
        __syncthreads();
    }
}

// ---------------- Phase D1: split-K flash attention for top queries --------
__global__ __launch_bounds__(256) void flash_part(int ntop)
{
    int bh  = blockIdx.y;
    int c   = blockIdx.x;          // key split
    int tid = threadIdx.x;

    __shared__ float qs[NTOPMAX * 65];
    __shared__ float Ks[TILE * 65];
    __shared__ float Vs[TILE * 65];
    __shared__ float sc[NTOPMAX * TILE];
    __shared__ int   pos[NTOPMAX];
    __shared__ int   smaxpos;

    if (tid < ntop) pos[tid] = g_top[bh * NTOPMAX + tid];
    __syncthreads();
    if (tid == 0) {
        int mp = 0;
        for (int u2 = 0; u2 < ntop; u2++) mp = max(mp, pos[u2]);
        smaxpos = mp;
    }
    for (int i = tid; i < ntop * DH; i += 256) {
        int u2 = i >> 6, d = i & 63;
        qs[u2 * 65 + d] = g_q[((size_t)bh * LSEQ + pos[u2]) * DH + d];
    }
    __syncthreads();
    const int maxpos = smaxpos;

    const int u      = tid >> 2;     // query row this thread's team owns
    const int qt     = tid & 3;      // quarter of the 64 output channels
    const bool active = (u < ntop);
    const int mypos  = active ? pos[u] : -1;

    float accv[16];
#pragma unroll
    for (int i = 0; i < 16; i++) accv[i] = 0.f;
    float rm = -INFINITY, rl = 0.f;

    for (int t = 0; t < CHUNK / TILE; t++) {
        int j0 = c * CHUNK + t * TILE;
        if (j0 > maxpos) break;

        for (int i = tid; i < TILE * DH; i += 256) {
            int r = i >> 6, d = i & 63;
            Ks[r * 65 + d] = g_k[((size_t)bh * LSEQ + j0 + r) * DH + d];
            Vs[r * 65 + d] = g_v[((size_t)bh * LSEQ + j0 + r) * DH + d];
        }
        __syncthreads();

        // scores: each thread computes 4 keys for one query
        for (int p = tid; p < ntop * (TILE / 4); p += 256) {
            int uu = p >> 3;
            int jq = (p & 7) * 4;
            const float* qrow = qs + uu * 65;
            float s0 = 0, s1 = 0, s2 = 0, s3 = 0;
#pragma unroll
            for (int d = 0; d < DH; d++) {
                float qv = qrow[d];
                s0 += qv * Ks[(jq + 0) * 65 + d];
                s1 += qv * Ks[(jq + 1) * 65 + d];
                s2 += qv * Ks[(jq + 2) * 65 + d];
                s3 += qv * Ks[(jq + 3) * 65 + d];
            }
            int pu = pos[uu];
            sc[uu * TILE + jq + 0] = (j0 + jq + 0 <= pu) ? s0 * SCALE : -INFINITY;
            sc[uu * TILE + jq + 1] = (j0 + jq + 1 <= pu) ? s1 * SCALE : -INFINITY;
            sc[uu * TILE + jq + 2] = (j0 + jq + 2 <= pu) ? s2 * SCALE : -INFINITY;
            sc[uu * TILE + jq + 3] = (j0 + jq + 3 <= pu) ? s3 * SCALE : -INFINITY;
        }
        __syncthreads();

        if (active && j0 <= mypos) {
            const float* srow = sc + u * TILE;
            float tm = -INFINITY;
#pragma unroll
            for (int j = 0; j < TILE; j++) tm = fmaxf(tm, srow[j]);
            if (tm != -INFINITY) {
                float nm    = fmaxf(rm, tm);
                float alpha = __expf(rm - nm);   // rm=-inf -> 0
                rl *= alpha;
#pragma unroll
                for (int i = 0; i < 16; i++) accv[i] *= alpha;
                float psum = 0.f;
                for (int j = 0; j < TILE; j++) {
                    float pj = __expf(srow[j] - nm);   // -inf -> 0
                    psum += pj;
                    const float* vrow = Vs + j * 65 + qt * 16;
#pragma unroll
                    for (int i = 0; i < 16; i++) accv[i] += pj * vrow[i];
                }
                rl += psum;
                rm = nm;
            }
        }
        __syncthreads();
    }

    if (active) {
        int base = (bh * SPLITS + c) * NTOPMAX + u;
        if (qt == 0) { g_pm[base] = rm; g_pl[base] = rl; }
        float* pa = g_pacc + (size_t)base * DH + qt * 16;
#pragma unroll
        for (int i = 0; i < 16; i++) pa[i] = accv[i];
    }
}

// ---------------- Phase D2: combine split-K partials -----------------------
__global__ __launch_bounds__(64) void flash_reduce(int ntop)
{
    int u = blockIdx.x, bh = blockIdx.y, d = threadIdx.x;
    float M = -INFINITY;
    for (int cc = 0; cc < SPLITS; cc++)
        M = fmaxf(M, g_pm[(bh * SPLITS + cc) * NTOPMAX + u]);
    float Ls = 0.f, od = 0.f;
    for (int cc = 0; cc < SPLITS; cc++) {
        int base  = (bh * SPLITS + cc) * NTOPMAX + u;
        float pmv = g_pm[base];
        if (pmv == -INFINITY) continue;
        float w = __expf(pmv - M);
        Ls += g_pl[base] * w;
        od += g_pacc[(size_t)base * DH + d] * w;
    }
    g_upd[(bh * NTOPMAX + u) * DH + d] = od / Ls;
}

// ---------------- Phase E: cumsum(v) over L, two-pass scan -----------------
__global__ __launch_bounds__(64) void chunk_sums()
{
    int bh = blockIdx.y, c = blockIdx.x, d = threadIdx.x;
    const float* vp = g_v + ((size_t)bh * LSEQ + c * 64) * DH + d;
    float s = 0.f;
#pragma unroll 8
    for (int r = 0; r < 64; r++) s += vp[(size_t)r * DH];
    g_csum[(bh * 64 + c) * DH + d] = s;
}

__global__ __launch_bounds__(64) void cumsum_out(float* __restrict__ out)
{
    int bh = blockIdx.y, c = blockIdx.x, d = threadIdx.x;
    float off = 0.f;
    for (int cc = 0; cc < c; cc++) off += g_csum[(bh * 64 + cc) * DH + d];
    const float* vp = g_v + ((size_t)bh * LSEQ + c * 64) * DH + d;
    int b = bh >> 3, h = bh & 7;
    float* op = out + ((size_t)b * LSEQ + c * 64) * DMODEL + h * DH + d;
    float acc = off;
    for (int r = 0; r < 64; r++) {
        acc += vp[(size_t)r * DH];
        op[(size_t)r * DMODEL] = acc;
    }
}

// ---------------- Phase F: scatter attention rows over cumsum --------------
__global__ __launch_bounds__(64) void scatter_upd(float* __restrict__ out, int ntop)
{
    int u = blockIdx.x, bh = blockIdx.y, d = threadIdx.x;
    int b = bh >> 3, h = bh & 7;
    int p = g_top[bh * NTOPMAX + u];
    out[((size_t)b * LSEQ + p) * DMODEL + h * DH + d] =
        g_upd[(bh * NTOPMAX + u) * DH + d];
}

// ---------------- launch ---------------------------------------------------
extern "C" void kernel_launch(void* const* d_in, const int* in_sizes, int n_in,
                              void* d_out, int out_size)
{
    const float* q_in = (const float*)d_in[0];
    const float* k_in = (const float*)d_in[1];
    const float* v_in = (const float*)d_in[2];
    const float* Wq   = (const float*)d_in[3];
    const float* bq   = (const float*)d_in[4];
    const float* Wk   = (const float*)d_in[5];
    const float* bk   = (const float*)d_in[6];
    const float* Wv   = (const float*)d_in[7];
    const float* bv   = (const float*)d_in[8];
    const int*   idxs = (const int*)d_in[9];
    float*       out  = (float*)d_out;

    int S    = in_sizes[9] / LSEQ;   // 45
    int ntop = S < NTOPMAX ? S : NTOPMAX;

    cudaFuncSetAttribute(proj_tc, cudaFuncAttributeMaxDynamicSharedMemorySize,
                         PROJ_SMEM);

    convert_A<<<dim3(MTOT * DMODEL / (256 * 4), 1, 3), 256>>>(q_in, k_in, v_in);
    convert_W<<<dim3(DMODEL * DMODEL / 256, 1, 3), 256>>>(Wq, Wk, Wv);
    proj_tc<<<dim3(DMODEL / 128, MTOT / 128, 3), 256, PROJ_SMEM>>>(bq, bk, bv);
    sample_m<<<dim3(LSEQ / 4, BHN), 128>>>(idxs, S);
    topk_sel<<<BHN, 256>>>(ntop);
    flash_part<<<dim3(SPLITS, BHN), 256>>>(ntop);
    flash_reduce<<<dim3(ntop, BHN), 64>>>(ntop);
    chunk_sums<<<dim3(64, BHN), 64>>>();
    cumsum_out<<<dim3(64, BHN), 64>>>(out);
    scatter_upd<<<dim3(ntop, BHN), 64>>>(out, ntop);
}